// round 4
// baseline (speedup 1.0000x reference)
#include <cuda_runtime.h>

// Problem shape (fixed by reference setup_inputs)
#define B_   16
#define Y_   32
#define HW_  65536                 // H*W = 256*256
#define NPIX (B_ * HW_)            // 1048576
#define THREADS 256
#define NBLOCKS (NPIX / THREADS)   // 4096
#define DIST_IND 7.0f

__device__ double g_partials[NBLOCKS];
__device__ unsigned int g_count = 0;

__global__ void __launch_bounds__(THREADS, 4)
disturbance_loss_fused(const float* __restrict__ out, float* __restrict__ d_out) {
    const int p  = blockIdx.x * THREADS + threadIdx.x;  // pixel id
    const int b  = p >> 16;                              // p / HW_
    const int hw = p & (HW_ - 1);
    const float* __restrict__ base = out + (size_t)b * (Y_ * HW_) + hw;

    // Load the whole Y-column into registers: 32 independent LDGs, front-batched
    // by ptxas -> MLP=32, one exposed DRAM latency per thread.
    float v[Y_];
#pragma unroll
    for (int y = 0; y < Y_; ++y)
        v[y] = __ldg(base + y * HW_);

    // Totals over all 32 rows (2-way ILP trees: halves the dependent-chain depth).
    float a0 = 0.f, c0 = 0.f, a1 = 0.f, c1 = 0.f, a2 = 0.f, c2 = 0.f;
#pragma unroll
    for (int y = 0; y < Y_; y += 2) {
        float u = v[y], w = v[y + 1];
        a0 += u;                          c0 += w;
        a1 = fmaf((float)y, u, a1);       c1 = fmaf((float)(y + 1), w, c1);
        a2 = fmaf(u, u, a2);              c2 = fmaf(w, w, c2);
    }
    const float T0 = a0 + c0, T1 = a1 + c1, T2 = a2 + c2;

    // Min of interior diffs (y in [2,30]); only its relation to -7 matters.
    float m1 = 0.f, m2 = 0.f;
#pragma unroll
    for (int y = 2; y <= Y_ - 2; y += 2) m1 = fminf(m1, v[y] - v[y - 1]);
#pragma unroll
    for (int y = 3; y <= Y_ - 2; y += 2) m2 = fminf(m2, v[y] - v[y - 1]);
    const float dmin = fminf(m1, m2);

    // f=0 unless some diff beats the -DIST_IND sentinel (p ~ 4e-7 per element).
    int   f = 0;
    float s0 = 0.f, s1 = 0.f, s2 = 0.f;   // before-segment snapshots (sum v, t*v, v*v)

    if (__ballot_sync(0xFFFFFFFFu, dmin < -DIST_IND)) {
        // Rare slow path: exact sequential first-occurrence argmin with
        // prefix-sum snapshots (matches jnp.argmin semantics).
        float best = -DIST_IND;
        float q0 = 0.f, q1 = 0.f, q2 = 0.f;
#pragma unroll
        for (int y = 0; y < Y_; ++y) {
            float u = v[y];
            if (y >= 2 && y <= Y_ - 2) {
                float d = u - v[y - 1];
                if (d < best) { best = d; f = y; s0 = q0; s1 = q1; s2 = q2; }
            }
            q0 += u;
            q1 = fmaf((float)y, u, q1);
            q2 = fmaf(u, u, q2);
        }
    }

    // Closed-form regression + residuals for both segments.
    const float ff = (float)f;
    const int   m  = Y_ - f;

    const float n_b   = ff;
    const float sx_b  = (float)(f * (f - 1) / 2);
    const float sxx_b = (float)((f - 1) * f * (2 * f - 1) / 6);
    const float sy_b  = s0, sxy_b = s1, syy_b = s2;

    const float n_a   = (float)m;
    const float sx_a  = (float)(m * (m - 1) / 2);
    const float sxx_a = (float)((m - 1) * m * (2 * m - 1) / 6);
    const float sy_a  = T0 - s0;
    const float sxy_a = (T1 - s1) - ff * sy_a;
    const float syy_a = T2 - s2;

    float contrib = 0.f;
    {   // before
        float ns  = fmaxf(n_b, 1.0f);
        float cov = sxy_b - sx_b * sy_b / ns;
        float var = sxx_b - sx_b * sx_b / ns;
        float vs  = (var > 0.f) ? var : 1.f;
        float s   = fminf(fmaxf(cov / vs, 0.f), 2.f);
        float c   = (sy_b - s * sx_b) / ns;
        float res = syy_b - 2.f * s * sxy_b - 2.f * c * sy_b
                  + s * s * sxx_b + 2.f * s * c * sx_b + c * c * n_b;
        if (n_b >= 3.f) contrib += res;
    }
    {   // after
        float ns  = fmaxf(n_a, 1.0f);
        float cov = sxy_a - sx_a * sy_a / ns;
        float var = sxx_a - sx_a * sx_a / ns;
        float vs  = (var > 0.f) ? var : 1.f;
        float s   = fminf(fmaxf(cov / vs, 0.f), 2.f);
        float c   = (sy_a - s * sx_a) / ns;
        float res = syy_a - 2.f * s * sxy_a - 2.f * c * sy_a
                  + s * s * sxx_a + 2.f * s * c * sx_a + c * c * n_a;
        if (n_a >= 3.f) contrib += res;
    }

    // ---- deterministic in-block reduction ----
    const unsigned lane = threadIdx.x & 31u;
    const unsigned wid  = threadIdx.x >> 5;
    float w = contrib;
#pragma unroll
    for (int o = 16; o > 0; o >>= 1)
        w += __shfl_down_sync(0xFFFFFFFFu, w, o);

    __shared__ float warpsum[THREADS / 32];
    if (lane == 0) warpsum[wid] = w;
    __syncthreads();

    __shared__ bool is_last;
    if (wid == 0) {
        float t = (lane < THREADS / 32) ? warpsum[lane] : 0.f;
#pragma unroll
        for (int o = 4; o > 0; o >>= 1)
            t += __shfl_down_sync(0xFFFFFFFFu, t, o);
        if (lane == 0) {
            g_partials[blockIdx.x] = (double)t;
            __threadfence();
            unsigned done = atomicAdd(&g_count, 1u);
            is_last = (done == (unsigned)(NBLOCKS - 1));
        }
    }
    __syncthreads();

    // ---- last block sums all partials in fixed index order (deterministic) ----
    if (is_last) {
        __threadfence();
        double s = 0.0;
#pragma unroll
        for (int k = 0; k < NBLOCKS / THREADS; ++k)
            s += g_partials[threadIdx.x + k * THREADS];
#pragma unroll
        for (int o = 16; o > 0; o >>= 1)
            s += __shfl_down_sync(0xFFFFFFFFu, s, o);
        __shared__ double wsum[THREADS / 32];
        if (lane == 0) wsum[wid] = s;
        __syncthreads();
        if (wid == 0) {
            double t = (lane < THREADS / 32) ? wsum[lane] : 0.0;
#pragma unroll
            for (int o = 4; o > 0; o >>= 1)
                t += __shfl_down_sync(0xFFFFFFFFu, t, o);
            if (lane == 0) {
                d_out[0] = (float)(t / ((double)Y_ * (double)NPIX));
                g_count = 0;   // reset for next graph replay
            }
        }
    }
}

extern "C" void kernel_launch(void* const* d_in, const int* in_sizes, int n_in,
                              void* d_out, int out_size) {
    const float* out = (const float*)d_in[0];   // 'target' (d_in[1]) unused by reference
    (void)in_sizes; (void)n_in; (void)out_size;
    disturbance_loss_fused<<<NBLOCKS, THREADS>>>(out, (float*)d_out);
}